// round 6
// baseline (speedup 1.0000x reference)
#include <cuda_runtime.h>

// ---------------------------------------------------------------------------
// FeaturePropagation: 3-NN inverse-distance interpolation + 3x (1x1 conv ->
// batch-stats BatchNorm -> ReLU).
//
// NUMERICS (calibrated against the reference over R2/R4 evidence):
//  * distance einsum (K=3): XLA fuses it elementwise -> EXACT fp32 with per-op
//    rounding. We replicate: separate __fmul_rn/__fadd_rn, no FMA contraction,
//    same association order as the reference expression.
//  * conv einsums (K=384/512/256): cuBLAS TF32. We replicate: operands rounded
//    to TF32 (cvt.rna.tf32.f32), exact fp32 products, fp32 accumulation.
//  * everything else: plain fp32.
// ---------------------------------------------------------------------------

namespace {
constexpr int B_   = 4;
constexpr int NY_  = 16384;
constexpr int NX_  = 4096;
constexpr int CY_  = 128;
constexpr int CX_  = 256;
constexpr int DIM_ = 384;               // CY + CX
constexpr int NP_  = B_ * NY_;          // 65536 total points
constexpr int C1_  = 512, C2_ = 256, C3_ = 128;
constexpr int NCHUNK_   = 128;          // BN reduction chunks
constexpr int CHUNKPTS_ = NP_ / NCHUNK_; // 512 points per chunk
}

__device__ __forceinline__ float tf32r(float x) {
    unsigned u = __float_as_uint(x), v;
    asm("cvt.rna.tf32.f32 %0, %1;" : "=r"(v) : "r"(u));
    return __uint_as_float(v);
}

// ----------------------------- scratch (device globals; no allocs) ----------
__device__ float g_X0[(long long)NP_ * DIM_];
__device__ float g_H1[(long long)NP_ * C1_];
__device__ float g_H2[(long long)NP_ * C2_];
__device__ float g_H3[(long long)NP_ * C3_];
__device__ float g_psum[NCHUNK_ * 512];
__device__ float g_psq [NCHUNK_ * 512];
__device__ float g_a[512];
__device__ float g_sh[512];

// ----------------------------- kernel 1: KNN + interpolation ----------------
// One block = 256 y-points of one batch. x-points cached in 64KB smem as
// (x, y, z, |x|^2) with |x|^2 = (x*x + y*y) + z*z in strict per-op fp32.
// Per candidate:  d = (|y|^2 + |x|^2) - 2*((y0x0 + y1x1) + y2x2)
// with every mul/add individually rounded (no fma) -- bit-matching the
// reference's XLA fusion so near-tie neighbor selection agrees.
__global__ void knn_interp_kernel(const float* __restrict__ yp,
                                  const float* __restrict__ yf,
                                  const float* __restrict__ xp,
                                  const float* __restrict__ xf) {
    extern __shared__ float4 sx[];          // [NX_]
    __shared__ int   s_idx[256][3];
    __shared__ float s_w[256][3];

    const int b     = blockIdx.y;
    const int ybase = blockIdx.x * 256;
    const int tid   = threadIdx.x;

    for (int j = tid; j < NX_; j += 256) {
        const float* p = xp + ((long long)b * NX_ + j) * 3;
        float x = p[0], y = p[1], z = p[2];
        float nrm = __fadd_rn(__fadd_rn(__fmul_rn(x, x), __fmul_rn(y, y)),
                              __fmul_rn(z, z));
        sx[j] = make_float4(x, y, z, nrm);
    }
    __syncthreads();

    const int n = ybase + tid;
    const float* q = yp + ((long long)b * NY_ + n) * 3;
    const float qx = q[0], qy = q[1], qz = q[2];
    const float qn = __fadd_rn(__fadd_rn(__fmul_rn(qx, qx), __fmul_rn(qy, qy)),
                               __fmul_rn(qz, qz));

    float d0 = 3.4e38f, d1 = 3.4e38f, d2 = 3.4e38f;
    int   i0 = 0, i1 = 0, i2 = 0;
#pragma unroll 8
    for (int j = 0; j < NX_; ++j) {
        float4 s = sx[j];
        float dot = __fadd_rn(__fadd_rn(__fmul_rn(qx, s.x), __fmul_rn(qy, s.y)),
                              __fmul_rn(qz, s.z));
        float t = __fadd_rn(__fadd_rn(qn, s.w), -2.f * dot);  // 2*dot exact
        if (t < d2) {
            if (t < d1) {
                d2 = d1; i2 = i1;
                if (t < d0) { d1 = d0; i1 = i0; d0 = t; i0 = j; }
                else        { d1 = t;  i1 = j; }
            } else { d2 = t; i2 = j; }
        }
    }
    float w0 = 1.f / (d0 + 1e-8f);
    float w1 = 1.f / (d1 + 1e-8f);
    float w2 = 1.f / (d2 + 1e-8f);
    const float ws = w0 + w1 + w2;
    w0 /= ws; w1 /= ws; w2 /= ws;
    s_idx[tid][0] = i0; s_idx[tid][1] = i1; s_idx[tid][2] = i2;
    s_w[tid][0] = w0;   s_w[tid][1] = w1;   s_w[tid][2] = w2;
    __syncthreads();

    const int lane = tid & 31, wrp = tid >> 5;
    for (int yy = wrp; yy < 256; yy += 8) {
        const long long pg = (long long)b * NY_ + ybase + yy;
        const float* f0 = xf + ((long long)b * NX_ + s_idx[yy][0]) * CX_;
        const float* f1 = xf + ((long long)b * NX_ + s_idx[yy][1]) * CX_;
        const float* f2 = xf + ((long long)b * NX_ + s_idx[yy][2]) * CX_;
        const float u0 = s_w[yy][0], u1 = s_w[yy][1], u2 = s_w[yy][2];
        float* dst = g_X0 + pg * DIM_;
        const float* src = yf + pg * CY_;
        for (int c = lane; c < CY_; c += 32) dst[c] = src[c];
        for (int c = lane; c < CX_; c += 32)
            dst[CY_ + c] = u0 * f0[c] + u1 * f1[c] + u2 * f2[c];
    }
}

// ----------------------------- kernel 2: NT SGEMM (TF32-emulating) ----------
// C[n][m] = sum_k tf32(X[n][k]) * tf32(W[m][k]) + bias[m], fp32 accumulate.
// 128x128 block tile, BK=16, 256 threads, 8x8 microtiles.
template <int BM, int BN, int BK, int TM, int TN>
__global__ __launch_bounds__(256)
void gemm_nt_kernel(const float* __restrict__ W,
                    const float* __restrict__ X,
                    const float* __restrict__ bias,
                    float* __restrict__ C,
                    int M, int N, int K) {
    __shared__ float Ws[BK][BM];
    __shared__ float Xs[BK][BN];
    const int tid = threadIdx.x;
    const int m0  = blockIdx.y * BM;
    const int n0  = blockIdx.x * BN;
    const int tm  = tid >> 4;   // 0..15
    const int tn  = tid & 15;   // 0..15

    float acc[TN][TM];
#pragma unroll
    for (int j = 0; j < TN; ++j)
#pragma unroll
        for (int i = 0; i < TM; ++i) acc[j][i] = 0.f;

    for (int k0 = 0; k0 < K; k0 += BK) {
#pragma unroll
        for (int l = 0; l < 2; ++l) {
            const int f = tid + l * 256;           // 0..511 float4 slots
            const int r = f >> 2;                  // tile row (0..127)
            const int k = (f & 3) * 4;             // k offset within BK
            float4 v = *reinterpret_cast<const float4*>(
                &W[(long long)(m0 + r) * K + k0 + k]);
            Ws[k + 0][r] = tf32r(v.x); Ws[k + 1][r] = tf32r(v.y);
            Ws[k + 2][r] = tf32r(v.z); Ws[k + 3][r] = tf32r(v.w);
            float4 u = *reinterpret_cast<const float4*>(
                &X[(long long)(n0 + r) * K + k0 + k]);
            Xs[k + 0][r] = tf32r(u.x); Xs[k + 1][r] = tf32r(u.y);
            Xs[k + 2][r] = tf32r(u.z); Xs[k + 3][r] = tf32r(u.w);
        }
        __syncthreads();
#pragma unroll
        for (int k = 0; k < BK; ++k) {
            float aw[TM], axr[TN];
            *reinterpret_cast<float4*>(aw)      = *reinterpret_cast<const float4*>(&Ws[k][tm * TM]);
            *reinterpret_cast<float4*>(aw + 4)  = *reinterpret_cast<const float4*>(&Ws[k][tm * TM + 4]);
            *reinterpret_cast<float4*>(axr)     = *reinterpret_cast<const float4*>(&Xs[k][tn * TN]);
            *reinterpret_cast<float4*>(axr + 4) = *reinterpret_cast<const float4*>(&Xs[k][tn * TN + 4]);
#pragma unroll
            for (int j = 0; j < TN; ++j)
#pragma unroll
                for (int i = 0; i < TM; ++i)
                    acc[j][i] = fmaf(axr[j], aw[i], acc[j][i]);
        }
        __syncthreads();
    }

    float bv[TM];
#pragma unroll
    for (int i = 0; i < TM; ++i) bv[i] = bias[m0 + tm * TM + i];
#pragma unroll
    for (int j = 0; j < TN; ++j) {
        const long long row = (long long)(n0 + tn * TN + j) * M + m0 + tm * TM;
        float4 v0 = make_float4(acc[j][0] + bv[0], acc[j][1] + bv[1],
                                acc[j][2] + bv[2], acc[j][3] + bv[3]);
        float4 v1 = make_float4(acc[j][4] + bv[4], acc[j][5] + bv[5],
                                acc[j][6] + bv[6], acc[j][7] + bv[7]);
        *reinterpret_cast<float4*>(&C[row])     = v0;
        *reinterpret_cast<float4*>(&C[row + 4]) = v1;
    }
}

// ----------------------------- BN kernels -----------------------------------
// Stage 1: deterministic per-chunk sums (blockDim = C, lane = channel).
__global__ void bn_partial_kernel(const float* __restrict__ H, int C,
                                  float* __restrict__ psum,
                                  float* __restrict__ psq) {
    const int c = threadIdx.x;
    const long long base = (long long)blockIdx.x * CHUNKPTS_;
    float s = 0.f, s2 = 0.f;
    for (int p = 0; p < CHUNKPTS_; ++p) {
        float v = H[(base + p) * C + c];
        s += v;
        s2 = fmaf(v, v, s2);
    }
    psum[blockIdx.x * C + c] = s;
    psq [blockIdx.x * C + c] = s2;
}

// Stage 2: fold chunks, emit fused scale a[c] and shift sh[c]:
//   y = relu(h * a[c] + sh[c])
__global__ void bn_finalize_kernel(const float* __restrict__ psum,
                                   const float* __restrict__ psq,
                                   const float* __restrict__ g,
                                   const float* __restrict__ be,
                                   int C,
                                   float* __restrict__ a,
                                   float* __restrict__ sh) {
    const int c = threadIdx.x;
    float s = 0.f, s2 = 0.f;
    for (int i = 0; i < NCHUNK_; ++i) { s += psum[i * C + c]; s2 += psq[i * C + c]; }
    const float inv = 1.f / (float)NP_;
    const float mu  = s * inv;
    const float var = s2 * inv - mu * mu;
    const float r   = rsqrtf(var + 1e-5f);
    const float aa  = g[c] * r;
    a[c]  = aa;
    sh[c] = be[c] - mu * aa;
}

// Stage 3: in-place normalize + relu, vectorized float4 (C % 4 == 0).
__global__ void bn_apply_kernel(float* __restrict__ H,
                                const float* __restrict__ a,
                                const float* __restrict__ sh,
                                int C, long long total) {
    const long long n4 = total >> 2;
    for (long long i = (long long)blockIdx.x * blockDim.x + threadIdx.x;
         i < n4; i += (long long)gridDim.x * blockDim.x) {
        float4 v = reinterpret_cast<float4*>(H)[i];
        const int c0 = (int)((i * 4) % C);
        v.x = fmaxf(0.f, fmaf(v.x, a[c0 + 0], sh[c0 + 0]));
        v.y = fmaxf(0.f, fmaf(v.y, a[c0 + 1], sh[c0 + 1]));
        v.z = fmaxf(0.f, fmaf(v.z, a[c0 + 2], sh[c0 + 2]));
        v.w = fmaxf(0.f, fmaf(v.w, a[c0 + 3], sh[c0 + 3]));
        reinterpret_cast<float4*>(H)[i] = v;
    }
}

// Final layer: normalize + relu + transpose [NP][128] -> out [B][128][NY].
// 32-point x 128-channel tile through smem so both global sides coalesce.
__global__ void bn_final_out_kernel(const float* __restrict__ H,
                                    const float* __restrict__ a,
                                    const float* __restrict__ sh,
                                    float* __restrict__ out) {
    __shared__ float t[C3_][33];
    const int tid = threadIdx.x;
    const int p0  = blockIdx.x * 32;
    for (int idx = tid; idx < 32 * C3_; idx += 256) {
        const int pl = idx >> 7;        // point within tile
        const int c  = idx & 127;       // channel
        t[c][pl] = H[(long long)(p0 + pl) * C3_ + c];
    }
    __syncthreads();
    for (int idx = tid; idx < C3_ * 32; idx += 256) {
        const int c  = idx >> 5;
        const int pl = idx & 31;
        const float v = fmaxf(0.f, fmaf(t[c][pl], a[c], sh[c]));
        const int p = p0 + pl;
        const int b = p >> 14;          // p / NY_
        const int n = p & (NY_ - 1);
        out[((long long)b * C3_ + c) * NY_ + n] = v;
    }
}

// ----------------------------- launch ---------------------------------------
extern "C" void kernel_launch(void* const* d_in, const int* in_sizes, int n_in,
                              void* d_out, int out_size) {
    (void)in_sizes; (void)n_in; (void)out_size;
    const float* yp  = (const float*)d_in[0];
    const float* yf  = (const float*)d_in[1];
    const float* xp  = (const float*)d_in[2];
    const float* xf  = (const float*)d_in[3];
    const float* W1  = (const float*)d_in[4];
    const float* b1  = (const float*)d_in[5];
    const float* g1  = (const float*)d_in[6];
    const float* be1 = (const float*)d_in[7];
    const float* W2  = (const float*)d_in[8];
    const float* b2  = (const float*)d_in[9];
    const float* g2  = (const float*)d_in[10];
    const float* be2 = (const float*)d_in[11];
    const float* W3  = (const float*)d_in[12];
    const float* b3  = (const float*)d_in[13];
    const float* g3  = (const float*)d_in[14];
    const float* be3 = (const float*)d_in[15];
    float* out = (float*)d_out;

    float *X0, *H1, *H2, *H3, *psum, *psq, *a, *sh;
    cudaGetSymbolAddress((void**)&X0,   g_X0);
    cudaGetSymbolAddress((void**)&H1,   g_H1);
    cudaGetSymbolAddress((void**)&H2,   g_H2);
    cudaGetSymbolAddress((void**)&H3,   g_H3);
    cudaGetSymbolAddress((void**)&psum, g_psum);
    cudaGetSymbolAddress((void**)&psq,  g_psq);
    cudaGetSymbolAddress((void**)&a,    g_a);
    cudaGetSymbolAddress((void**)&sh,   g_sh);

    // 1) KNN + interpolation -> X0 [NP][384]
    static int smem_set = 0;
    if (!smem_set) {
        cudaFuncSetAttribute(knn_interp_kernel,
                             cudaFuncAttributeMaxDynamicSharedMemorySize,
                             NX_ * (int)sizeof(float4));
        smem_set = 1;
    }
    knn_interp_kernel<<<dim3(NY_ / 256, B_), 256, NX_ * sizeof(float4)>>>(yp, yf, xp, xf);

    // 2) Layer 1: 384 -> 512
    gemm_nt_kernel<128, 128, 16, 8, 8>
        <<<dim3(NP_ / 128, C1_ / 128), 256>>>(W1, X0, b1, H1, C1_, NP_, DIM_);
    bn_partial_kernel<<<NCHUNK_, C1_>>>(H1, C1_, psum, psq);
    bn_finalize_kernel<<<1, C1_>>>(psum, psq, g1, be1, C1_, a, sh);
    bn_apply_kernel<<<2048, 256>>>(H1, a, sh, C1_, (long long)NP_ * C1_);

    // 3) Layer 2: 512 -> 256
    gemm_nt_kernel<128, 128, 16, 8, 8>
        <<<dim3(NP_ / 128, C2_ / 128), 256>>>(W2, H1, b2, H2, C2_, NP_, C1_);
    bn_partial_kernel<<<NCHUNK_, C2_>>>(H2, C2_, psum, psq);
    bn_finalize_kernel<<<1, C2_>>>(psum, psq, g2, be2, C2_, a, sh);
    bn_apply_kernel<<<2048, 256>>>(H2, a, sh, C2_, (long long)NP_ * C2_);

    // 4) Layer 3: 256 -> 128, fused final normalize+relu+transpose
    gemm_nt_kernel<128, 128, 16, 8, 8>
        <<<dim3(NP_ / 128, C3_ / 128), 256>>>(W3, H2, b3, H3, C3_, NP_, C2_);
    bn_partial_kernel<<<NCHUNK_, C3_>>>(H3, C3_, psum, psq);
    bn_finalize_kernel<<<1, C3_>>>(psum, psq, g3, be3, C3_, a, sh);
    bn_final_out_kernel<<<NP_ / 32, 256>>>(H3, a, sh, out);
}

// round 8
// speedup vs baseline: 1.9664x; 1.9664x over previous
#include <cuda_runtime.h>

// ---------------------------------------------------------------------------
// FeaturePropagation: 3-NN inverse-distance interpolation + 3x (1x1 conv ->
// batch-stats BatchNorm -> ReLU).
//
// NUMERICS (validated in R6, rel_err 6.7e-4):
//  * distance einsum: exact fp32, per-op rounding (no FMA), XLA association.
//  * conv einsums: TF32 operands (cvt.rna) + fp32 accumulation, now executed
//    on the tensor pipe via mma.sync.m16n8k8.tf32 (baseline PTX -- the
//    tcgen05 family needs the sm_103a feature target, which this toolchain's
//    ptxas pass does not enable). Element values identical to R6; only
//    accumulation order differs.
//  * BN normalize+relu fused into next layer's GEMM A-staging (same math).
// ---------------------------------------------------------------------------

namespace {
constexpr int B_   = 4;
constexpr int NY_  = 16384;
constexpr int NX_  = 4096;
constexpr int CY_  = 128;
constexpr int CX_  = 256;
constexpr int DIM_ = 384;               // CY + CX
constexpr int NP_  = B_ * NY_;          // 65536 total points
constexpr int C1_  = 512, C2_ = 256, C3_ = 128;
constexpr int NCHUNK_   = 128;          // BN reduction chunks
constexpr int CHUNKPTS_ = NP_ / NCHUNK_; // 512 points per chunk
constexpr int SSTR_ = 36;               // smem row stride (floats), pad 4
}

__device__ __forceinline__ float tf32r(float x) {
    unsigned u = __float_as_uint(x), v;
    asm("cvt.rna.tf32.f32 %0, %1;" : "=r"(v) : "r"(u));
    return __uint_as_float(v);
}

// ----------------------------- scratch (device globals; no allocs) ----------
__device__ float g_X0[(long long)NP_ * DIM_];
__device__ float g_H1[(long long)NP_ * C1_];
__device__ float g_H2[(long long)NP_ * C2_];
__device__ float g_H3[(long long)NP_ * C3_];
__device__ float g_psum[NCHUNK_ * 512];
__device__ float g_psq [NCHUNK_ * 512];
__device__ float g_a[512];
__device__ float g_sh[512];

// ----------------------------- kernel 1: KNN + interpolation ----------------
__global__ void knn_interp_kernel(const float* __restrict__ yp,
                                  const float* __restrict__ yf,
                                  const float* __restrict__ xp,
                                  const float* __restrict__ xf) {
    extern __shared__ float4 sx[];          // [NX_]
    __shared__ int   s_idx[256][3];
    __shared__ float s_w[256][3];

    const int b     = blockIdx.y;
    const int ybase = blockIdx.x * 256;
    const int tid   = threadIdx.x;

    for (int j = tid; j < NX_; j += 256) {
        const float* p = xp + ((long long)b * NX_ + j) * 3;
        float x = p[0], y = p[1], z = p[2];
        float nrm = __fadd_rn(__fadd_rn(__fmul_rn(x, x), __fmul_rn(y, y)),
                              __fmul_rn(z, z));
        sx[j] = make_float4(x, y, z, nrm);
    }
    __syncthreads();

    const int n = ybase + tid;
    const float* q = yp + ((long long)b * NY_ + n) * 3;
    const float qx = q[0], qy = q[1], qz = q[2];
    const float qn = __fadd_rn(__fadd_rn(__fmul_rn(qx, qx), __fmul_rn(qy, qy)),
                               __fmul_rn(qz, qz));

    float d0 = 3.4e38f, d1 = 3.4e38f, d2 = 3.4e38f;
    int   i0 = 0, i1 = 0, i2 = 0;
#pragma unroll 8
    for (int j = 0; j < NX_; ++j) {
        float4 s = sx[j];
        float dot = __fadd_rn(__fadd_rn(__fmul_rn(qx, s.x), __fmul_rn(qy, s.y)),
                              __fmul_rn(qz, s.z));
        float t = __fadd_rn(__fadd_rn(qn, s.w), -2.f * dot);
        if (t < d2) {
            if (t < d1) {
                d2 = d1; i2 = i1;
                if (t < d0) { d1 = d0; i1 = i0; d0 = t; i0 = j; }
                else        { d1 = t;  i1 = j; }
            } else { d2 = t; i2 = j; }
        }
    }
    float w0 = 1.f / (d0 + 1e-8f);
    float w1 = 1.f / (d1 + 1e-8f);
    float w2 = 1.f / (d2 + 1e-8f);
    const float ws = w0 + w1 + w2;
    w0 /= ws; w1 /= ws; w2 /= ws;
    s_idx[tid][0] = i0; s_idx[tid][1] = i1; s_idx[tid][2] = i2;
    s_w[tid][0] = w0;   s_w[tid][1] = w1;   s_w[tid][2] = w2;
    __syncthreads();

    const int lane = tid & 31, wrp = tid >> 5;
    for (int yy = wrp; yy < 256; yy += 8) {
        const long long pg = (long long)b * NY_ + ybase + yy;
        const float* f0 = xf + ((long long)b * NX_ + s_idx[yy][0]) * CX_;
        const float* f1 = xf + ((long long)b * NX_ + s_idx[yy][1]) * CX_;
        const float* f2 = xf + ((long long)b * NX_ + s_idx[yy][2]) * CX_;
        const float u0 = s_w[yy][0], u1 = s_w[yy][1], u2 = s_w[yy][2];
        float* dst = g_X0 + pg * DIM_;
        const float* src = yf + pg * CY_;
        for (int c = lane; c < CY_; c += 32) dst[c] = src[c];
        for (int c = lane; c < CX_; c += 32)
            dst[CY_ + c] = u0 * f0[c] + u1 * f1[c] + u2 * f2[c];
    }
}

// ----------------------------- kernel 2: tensor-core TF32 GEMM --------------
// C[n][m] = sum_k tf32(x[n][k]) * tf32(W[m][k]) + bias[m]
// where x = NORM ? relu(X*a[k]+sh[k]) : X   (fused BN-apply of prev layer)
//
// Block tile 128 points x 128 channels, BK=32. 8 warps: warp w -> point group
// (w&3)*32, channel group (w>>2)*64. Per warp 2x8 mma m16n8k8 tiles.
// Smem rows padded to 36 floats -> fragment LDS provably conflict-free.
// Register prefetch of chunk t+1 overlaps its global loads with chunk t MMAs.
template <bool NORM>
__global__ __launch_bounds__(256)
void gemm_mma_kernel(const float* __restrict__ W,   // [M][K]
                     const float* __restrict__ X,   // [NP][K]
                     const float* __restrict__ bias,
                     const float* __restrict__ an,  // per-k scale (NORM)
                     const float* __restrict__ sn,  // per-k shift (NORM)
                     float* __restrict__ C,         // [NP][M]
                     int M, int K) {
    __shared__ float As[128 * SSTR_];   // points   x k (BK=32)
    __shared__ float Bs[128 * SSTR_];   // channels x k

    const int tid  = threadIdx.x;
    const int lane = tid & 31;
    const int w    = tid >> 5;
    const int wn   = (w & 3) * 32;      // point offset of warp tile
    const int wm   = (w >> 2) * 64;     // channel offset of warp tile
    const int n0   = blockIdx.x * 128;
    const int m0   = blockIdx.y * 128;

    const int r  = tid >> 3;            // staging row 0..31 per loop step
    const int kk = (tid & 7) * 4;       // staging k offset

    float acc[2][8][4];
#pragma unroll
    for (int mt = 0; mt < 2; ++mt)
#pragma unroll
        for (int nt = 0; nt < 8; ++nt)
#pragma unroll
            for (int q = 0; q < 4; ++q) acc[mt][nt][q] = 0.f;

    const int ntiles = K >> 5;
    float4 px[4], pw[4];

    // prefetch chunk 0
#pragma unroll
    for (int l = 0; l < 4; ++l) {
        const int rr = r + l * 32;
        px[l] = *reinterpret_cast<const float4*>(&X[(long long)(n0 + rr) * K + kk]);
        pw[l] = *reinterpret_cast<const float4*>(&W[(long long)(m0 + rr) * K + kk]);
    }

    for (int t = 0; t < ntiles; ++t) {
        const int k0 = t << 5;
        // store prefetched chunk into smem (with NORM + tf32 rounding)
#pragma unroll
        for (int l = 0; l < 4; ++l) {
            const int rr = r + l * 32;
            float4 v = px[l];
            if (NORM) {
                v.x = fmaxf(0.f, fmaf(v.x, an[k0 + kk + 0], sn[k0 + kk + 0]));
                v.y = fmaxf(0.f, fmaf(v.y, an[k0 + kk + 1], sn[k0 + kk + 1]));
                v.z = fmaxf(0.f, fmaf(v.z, an[k0 + kk + 2], sn[k0 + kk + 2]));
                v.w = fmaxf(0.f, fmaf(v.w, an[k0 + kk + 3], sn[k0 + kk + 3]));
            }
            *reinterpret_cast<float4*>(&As[rr * SSTR_ + kk]) =
                make_float4(tf32r(v.x), tf32r(v.y), tf32r(v.z), tf32r(v.w));
            float4 wv = pw[l];
            *reinterpret_cast<float4*>(&Bs[rr * SSTR_ + kk]) =
                make_float4(tf32r(wv.x), tf32r(wv.y), tf32r(wv.z), tf32r(wv.w));
        }
        __syncthreads();
        // issue next chunk's global loads (latency hidden behind MMAs)
        if (t + 1 < ntiles) {
            const int kn = (t + 1) << 5;
#pragma unroll
            for (int l = 0; l < 4; ++l) {
                const int rr = r + l * 32;
                px[l] = *reinterpret_cast<const float4*>(&X[(long long)(n0 + rr) * K + kn + kk]);
                pw[l] = *reinterpret_cast<const float4*>(&W[(long long)(m0 + rr) * K + kn + kk]);
            }
        }
        // compute: 4 k-steps of 8
#pragma unroll
        for (int ks = 0; ks < 4; ++ks) {
            const int kb = ks * 8 + (lane & 3);
            unsigned a[2][4];
#pragma unroll
            for (int mt = 0; mt < 2; ++mt) {
                const int rowb = wn + mt * 16 + (lane >> 2);
                a[mt][0] = __float_as_uint(As[rowb * SSTR_ + kb]);
                a[mt][1] = __float_as_uint(As[(rowb + 8) * SSTR_ + kb]);
                a[mt][2] = __float_as_uint(As[rowb * SSTR_ + kb + 4]);
                a[mt][3] = __float_as_uint(As[(rowb + 8) * SSTR_ + kb + 4]);
            }
#pragma unroll
            for (int nt = 0; nt < 8; ++nt) {
                const int colb = wm + nt * 8 + (lane >> 2);
                unsigned b0 = __float_as_uint(Bs[colb * SSTR_ + kb]);
                unsigned b1 = __float_as_uint(Bs[colb * SSTR_ + kb + 4]);
#pragma unroll
                for (int mt = 0; mt < 2; ++mt) {
                    asm volatile(
                        "mma.sync.aligned.m16n8k8.row.col.f32.tf32.tf32.f32 "
                        "{%0,%1,%2,%3}, {%4,%5,%6,%7}, {%8,%9}, {%0,%1,%2,%3};"
                        : "+f"(acc[mt][nt][0]), "+f"(acc[mt][nt][1]),
                          "+f"(acc[mt][nt][2]), "+f"(acc[mt][nt][3])
                        : "r"(a[mt][0]), "r"(a[mt][1]), "r"(a[mt][2]), "r"(a[mt][3]),
                          "r"(b0), "r"(b1));
                }
            }
        }
        __syncthreads();
    }

    // epilogue: acc + bias -> C (c0/c1 and c2/c3 are adjacent columns)
#pragma unroll
    for (int mt = 0; mt < 2; ++mt) {
        const int row = n0 + wn + mt * 16 + (lane >> 2);
#pragma unroll
        for (int nt = 0; nt < 8; ++nt) {
            const int col = m0 + wm + nt * 8 + 2 * (lane & 3);
            const float bv0 = bias[col], bv1 = bias[col + 1];
            float2 v0 = make_float2(acc[mt][nt][0] + bv0, acc[mt][nt][1] + bv1);
            float2 v1 = make_float2(acc[mt][nt][2] + bv0, acc[mt][nt][3] + bv1);
            *reinterpret_cast<float2*>(&C[(long long)row * M + col])       = v0;
            *reinterpret_cast<float2*>(&C[(long long)(row + 8) * M + col]) = v1;
        }
    }
}

// ----------------------------- BN kernels -----------------------------------
// Stage 1: deterministic per-chunk sums (blockDim = C, lane = channel).
__global__ void bn_partial_kernel(const float* __restrict__ H, int C,
                                  float* __restrict__ psum,
                                  float* __restrict__ psq) {
    const int c = threadIdx.x;
    const long long base = (long long)blockIdx.x * CHUNKPTS_;
    float s = 0.f, s2 = 0.f;
    for (int p = 0; p < CHUNKPTS_; ++p) {
        float v = H[(base + p) * C + c];
        s += v;
        s2 = fmaf(v, v, s2);
    }
    psum[blockIdx.x * C + c] = s;
    psq [blockIdx.x * C + c] = s2;
}

// Stage 2: warp-per-channel chunk fold (parallel; deterministic shfl tree).
__global__ void bn_finalize_kernel(const float* __restrict__ psum,
                                   const float* __restrict__ psq,
                                   const float* __restrict__ g,
                                   const float* __restrict__ be,
                                   int C,
                                   float* __restrict__ a,
                                   float* __restrict__ sh) {
    const int c    = blockIdx.x * 8 + (threadIdx.x >> 5);
    const int lane = threadIdx.x & 31;
    float s = 0.f, s2 = 0.f;
#pragma unroll
    for (int i = lane; i < NCHUNK_; i += 32) { s += psum[i * C + c]; s2 += psq[i * C + c]; }
#pragma unroll
    for (int o = 16; o; o >>= 1) {
        s  += __shfl_xor_sync(0xFFFFFFFFu, s,  o);
        s2 += __shfl_xor_sync(0xFFFFFFFFu, s2, o);
    }
    if (lane == 0) {
        const float inv = 1.f / (float)NP_;
        const float mu  = s * inv;
        const float var = s2 * inv - mu * mu;
        const float r   = rsqrtf(var + 1e-5f);
        const float aa  = g[c] * r;
        a[c]  = aa;
        sh[c] = be[c] - mu * aa;
    }
}

// Final layer: normalize + relu + transpose [NP][128] -> out [B][128][NY].
__global__ void bn_final_out_kernel(const float* __restrict__ H,
                                    const float* __restrict__ a,
                                    const float* __restrict__ sh,
                                    float* __restrict__ out) {
    __shared__ float t[C3_][33];
    const int tid = threadIdx.x;
    const int p0  = blockIdx.x * 32;
    for (int idx = tid; idx < 32 * C3_; idx += 256) {
        const int pl = idx >> 7;        // point within tile
        const int c  = idx & 127;       // channel
        t[c][pl] = H[(long long)(p0 + pl) * C3_ + c];
    }
    __syncthreads();
    for (int idx = tid; idx < C3_ * 32; idx += 256) {
        const int c  = idx >> 5;
        const int pl = idx & 31;
        const float v = fmaxf(0.f, fmaf(t[c][pl], a[c], sh[c]));
        const int p = p0 + pl;
        const int b = p >> 14;          // p / NY_
        const int n = p & (NY_ - 1);
        out[((long long)b * C3_ + c) * NY_ + n] = v;
    }
}

// ----------------------------- launch ---------------------------------------
extern "C" void kernel_launch(void* const* d_in, const int* in_sizes, int n_in,
                              void* d_out, int out_size) {
    (void)in_sizes; (void)n_in; (void)out_size;
    const float* yp  = (const float*)d_in[0];
    const float* yf  = (const float*)d_in[1];
    const float* xp  = (const float*)d_in[2];
    const float* xf  = (const float*)d_in[3];
    const float* W1  = (const float*)d_in[4];
    const float* b1  = (const float*)d_in[5];
    const float* g1  = (const float*)d_in[6];
    const float* be1 = (const float*)d_in[7];
    const float* W2  = (const float*)d_in[8];
    const float* b2  = (const float*)d_in[9];
    const float* g2  = (const float*)d_in[10];
    const float* be2 = (const float*)d_in[11];
    const float* W3  = (const float*)d_in[12];
    const float* b3  = (const float*)d_in[13];
    const float* g3  = (const float*)d_in[14];
    const float* be3 = (const float*)d_in[15];
    float* out = (float*)d_out;

    float *X0, *H1, *H2, *H3, *psum, *psq, *a, *sh;
    cudaGetSymbolAddress((void**)&X0,   g_X0);
    cudaGetSymbolAddress((void**)&H1,   g_H1);
    cudaGetSymbolAddress((void**)&H2,   g_H2);
    cudaGetSymbolAddress((void**)&H3,   g_H3);
    cudaGetSymbolAddress((void**)&psum, g_psum);
    cudaGetSymbolAddress((void**)&psq,  g_psq);
    cudaGetSymbolAddress((void**)&a,    g_a);
    cudaGetSymbolAddress((void**)&sh,   g_sh);

    static int attr_set = 0;
    if (!attr_set) {
        cudaFuncSetAttribute(knn_interp_kernel,
                             cudaFuncAttributeMaxDynamicSharedMemorySize,
                             NX_ * (int)sizeof(float4));
        attr_set = 1;
    }

    // 1) KNN + interpolation -> X0 [NP][384]
    knn_interp_kernel<<<dim3(NY_ / 256, B_), 256, NX_ * sizeof(float4)>>>(yp, yf, xp, xf);

    // 2) Layer 1: 384 -> 512 (no input norm)
    gemm_mma_kernel<false><<<dim3(NP_ / 128, C1_ / 128), 256>>>(
        W1, X0, b1, nullptr, nullptr, H1, C1_, DIM_);
    bn_partial_kernel<<<NCHUNK_, C1_>>>(H1, C1_, psum, psq);
    bn_finalize_kernel<<<C1_ / 8, 256>>>(psum, psq, g1, be1, C1_, a, sh);

    // 3) Layer 2: 512 -> 256 (BN1+relu fused into A staging)
    gemm_mma_kernel<true><<<dim3(NP_ / 128, C2_ / 128), 256>>>(
        W2, H1, b2, a, sh, H2, C2_, C1_);
    bn_partial_kernel<<<NCHUNK_, C2_>>>(H2, C2_, psum, psq);
    bn_finalize_kernel<<<C2_ / 8, 256>>>(psum, psq, g2, be2, C2_, a, sh);

    // 4) Layer 3: 256 -> 128 (BN2+relu fused into A staging)
    gemm_mma_kernel<true><<<dim3(NP_ / 128, C3_ / 128), 256>>>(
        W3, H2, b3, a, sh, H3, C3_, C2_);
    bn_partial_kernel<<<NCHUNK_, C3_>>>(H3, C3_, psum, psq);
    bn_finalize_kernel<<<C3_ / 8, 256>>>(psum, psq, g3, be3, C3_, a, sh);

    // 5) final normalize + relu + transpose -> out [B,128,NY]
    bn_final_out_kernel<<<NP_ / 32, 256>>>(H3, a, sh, out);
}

// round 9
// speedup vs baseline: 2.2115x; 1.1246x over previous
#include <cuda_runtime.h>

// ---------------------------------------------------------------------------
// FeaturePropagation: 3-NN inverse-distance interpolation + 3x (1x1 conv ->
// batch-stats BatchNorm -> ReLU).
//
// NUMERICS (validated R6/R8, rel_err 6.7e-4):
//  * distance einsum: exact fp32, per-op rounding (no FMA), XLA association.
//  * conv einsums: TF32 operands (cvt.rna) + fp32 accumulation on the tensor
//    pipe via mma.sync.m16n8k8.tf32 (baseline PTX; tcgen05 needs the sm_103a
//    feature target which this toolchain's ptxas pass does not enable).
//  * BN normalize+relu fused into next layer's GEMM A-staging.
//  * BN statistics (per-channel sum / sum-of-squares) fused into the GEMM
//    epilogue: 512 deterministic 128-point chunks, folded by bn_finalize.
// ---------------------------------------------------------------------------

namespace {
constexpr int B_   = 4;
constexpr int NY_  = 16384;
constexpr int NX_  = 4096;
constexpr int CY_  = 128;
constexpr int CX_  = 256;
constexpr int DIM_ = 384;               // CY + CX
constexpr int NP_  = B_ * NY_;          // 65536 total points
constexpr int C1_  = 512, C2_ = 256, C3_ = 128;
constexpr int NCHUNK_ = NP_ / 128;      // 512 BN chunks (one per GEMM point tile)
constexpr int SSTR_ = 36;               // smem row stride (floats), pad 4

constexpr int gemm_smem_bytes(int BN) {
    return (128 + BN) * SSTR_ * 4 + 4 * BN * 4;   // As + Bs + reduction scratch
}
}

__device__ __forceinline__ float tf32r(float x) {
    unsigned u = __float_as_uint(x), v;
    asm("cvt.rna.tf32.f32 %0, %1;" : "=r"(v) : "r"(u));
    return __uint_as_float(v);
}

// ----------------------------- scratch (device globals; no allocs) ----------
__device__ float g_X0[(long long)NP_ * DIM_];
__device__ float g_H1[(long long)NP_ * C1_];
__device__ float g_H2[(long long)NP_ * C2_];
__device__ float g_H3[(long long)NP_ * C3_];
__device__ float g_psum[NCHUNK_ * 512];
__device__ float g_psq [NCHUNK_ * 512];
__device__ float g_a[512];
__device__ float g_sh[512];

// ----------------------------- kernel 1: KNN + interpolation ----------------
__global__ void knn_interp_kernel(const float* __restrict__ yp,
                                  const float* __restrict__ yf,
                                  const float* __restrict__ xp,
                                  const float* __restrict__ xf) {
    extern __shared__ float4 sx[];          // [NX_]
    __shared__ int   s_idx[256][3];
    __shared__ float s_w[256][3];

    const int b     = blockIdx.y;
    const int ybase = blockIdx.x * 256;
    const int tid   = threadIdx.x;

    for (int j = tid; j < NX_; j += 256) {
        const float* p = xp + ((long long)b * NX_ + j) * 3;
        float x = p[0], y = p[1], z = p[2];
        float nrm = __fadd_rn(__fadd_rn(__fmul_rn(x, x), __fmul_rn(y, y)),
                              __fmul_rn(z, z));
        sx[j] = make_float4(x, y, z, nrm);
    }
    __syncthreads();

    const int n = ybase + tid;
    const float* q = yp + ((long long)b * NY_ + n) * 3;
    const float qx = q[0], qy = q[1], qz = q[2];
    const float qn = __fadd_rn(__fadd_rn(__fmul_rn(qx, qx), __fmul_rn(qy, qy)),
                               __fmul_rn(qz, qz));

    float d0 = 3.4e38f, d1 = 3.4e38f, d2 = 3.4e38f;
    int   i0 = 0, i1 = 0, i2 = 0;
#pragma unroll 8
    for (int j = 0; j < NX_; ++j) {
        float4 s = sx[j];
        float dot = __fadd_rn(__fadd_rn(__fmul_rn(qx, s.x), __fmul_rn(qy, s.y)),
                              __fmul_rn(qz, s.z));
        float t = __fadd_rn(__fadd_rn(qn, s.w), -2.f * dot);
        if (t < d2) {
            if (t < d1) {
                d2 = d1; i2 = i1;
                if (t < d0) { d1 = d0; i1 = i0; d0 = t; i0 = j; }
                else        { d1 = t;  i1 = j; }
            } else { d2 = t; i2 = j; }
        }
    }
    float w0 = 1.f / (d0 + 1e-8f);
    float w1 = 1.f / (d1 + 1e-8f);
    float w2 = 1.f / (d2 + 1e-8f);
    const float ws = w0 + w1 + w2;
    w0 /= ws; w1 /= ws; w2 /= ws;
    s_idx[tid][0] = i0; s_idx[tid][1] = i1; s_idx[tid][2] = i2;
    s_w[tid][0] = w0;   s_w[tid][1] = w1;   s_w[tid][2] = w2;
    __syncthreads();

    const int lane = tid & 31, wrp = tid >> 5;
    for (int yy = wrp; yy < 256; yy += 8) {
        const long long pg = (long long)b * NY_ + ybase + yy;
        const float* f0 = xf + ((long long)b * NX_ + s_idx[yy][0]) * CX_;
        const float* f1 = xf + ((long long)b * NX_ + s_idx[yy][1]) * CX_;
        const float* f2 = xf + ((long long)b * NX_ + s_idx[yy][2]) * CX_;
        const float u0 = s_w[yy][0], u1 = s_w[yy][1], u2 = s_w[yy][2];
        float* dst = g_X0 + pg * DIM_;
        const float* src = yf + pg * CY_;
        for (int c = lane; c < CY_; c += 32) dst[c] = src[c];
        for (int c = lane; c < CX_; c += 32)
            dst[CY_ + c] = u0 * f0[c] + u1 * f1[c] + u2 * f2[c];
    }
}

// ----------------------------- kernel 2: tensor-core TF32 GEMM --------------
// C[n][m] = sum_k tf32(x[n][k]) * tf32(W[m][k]) + bias[m]
// where x = NORM ? relu(X*a[k]+sh[k]) : X   (fused BN-apply of prev layer).
// Epilogue also emits per-channel partial sums/squares of the output tile
// (this block's 128 points) into psum/psq[blockIdx.x][channel].
//
// Block tile 128 points x BN channels, BK=32. 8 warps: 2 point-groups x
// 4 channel-groups; warp tile 64 pts x BN/4 ch = 4 x (BN/32) mma m16n8k8.
// Smem rows padded to 36 floats -> fragment LDS conflict-free.
// Register prefetch of chunk t+1 overlaps global loads with chunk t MMAs.
template <int BN, bool NORM>
__global__ __launch_bounds__(256)
void gemm_mma_kernel(const float* __restrict__ W,   // [M][K]
                     const float* __restrict__ X,   // [NP][K]
                     const float* __restrict__ bias,
                     const float* __restrict__ an,  // per-k scale (NORM)
                     const float* __restrict__ sn,  // per-k shift (NORM)
                     float* __restrict__ C,         // [NP][M]
                     float* __restrict__ psum,
                     float* __restrict__ psq,
                     int M, int K) {
    extern __shared__ float smem[];
    float* As  = smem;                    // 128 x SSTR_
    float* Bs  = smem + 128 * SSTR_;      // BN  x SSTR_
    float* red = Bs + BN * SSTR_;         // 4*BN: [sum pg0|sum pg1|sq pg0|sq pg1]

    constexpr int NT = BN / 32;           // mma tiles per warp in channel dim
    const int tid  = threadIdx.x;
    const int lane = tid & 31;
    const int w    = tid >> 5;
    const int pg   = w & 1;               // point group
    const int wn   = pg * 64;
    const int wm   = (w >> 1) * (BN / 4); // channel offset of warp tile
    const int n0   = blockIdx.x * 128;
    const int m0   = blockIdx.y * BN;

    const int r  = tid >> 3;              // staging row 0..31 per step
    const int kk = (tid & 7) * 4;         // staging k offset

    float acc[4][NT][4];
#pragma unroll
    for (int mt = 0; mt < 4; ++mt)
#pragma unroll
        for (int nt = 0; nt < NT; ++nt)
#pragma unroll
            for (int q = 0; q < 4; ++q) acc[mt][nt][q] = 0.f;

    const int ntiles = K >> 5;
    float4 px[4], pw[NT];

    // prefetch chunk 0
#pragma unroll
    for (int l = 0; l < 4; ++l)
        px[l] = *reinterpret_cast<const float4*>(&X[(long long)(n0 + r + l * 32) * K + kk]);
#pragma unroll
    for (int l = 0; l < NT; ++l)
        pw[l] = *reinterpret_cast<const float4*>(&W[(long long)(m0 + r + l * 32) * K + kk]);

    for (int t = 0; t < ntiles; ++t) {
        const int k0 = t << 5;
#pragma unroll
        for (int l = 0; l < 4; ++l) {
            const int rr = r + l * 32;
            float4 v = px[l];
            if (NORM) {
                v.x = fmaxf(0.f, fmaf(v.x, an[k0 + kk + 0], sn[k0 + kk + 0]));
                v.y = fmaxf(0.f, fmaf(v.y, an[k0 + kk + 1], sn[k0 + kk + 1]));
                v.z = fmaxf(0.f, fmaf(v.z, an[k0 + kk + 2], sn[k0 + kk + 2]));
                v.w = fmaxf(0.f, fmaf(v.w, an[k0 + kk + 3], sn[k0 + kk + 3]));
            }
            *reinterpret_cast<float4*>(&As[rr * SSTR_ + kk]) =
                make_float4(tf32r(v.x), tf32r(v.y), tf32r(v.z), tf32r(v.w));
        }
#pragma unroll
        for (int l = 0; l < NT; ++l) {
            const int rr = r + l * 32;
            float4 wv = pw[l];
            *reinterpret_cast<float4*>(&Bs[rr * SSTR_ + kk]) =
                make_float4(tf32r(wv.x), tf32r(wv.y), tf32r(wv.z), tf32r(wv.w));
        }
        __syncthreads();
        if (t + 1 < ntiles) {
            const int kn = (t + 1) << 5;
#pragma unroll
            for (int l = 0; l < 4; ++l)
                px[l] = *reinterpret_cast<const float4*>(
                    &X[(long long)(n0 + r + l * 32) * K + kn + kk]);
#pragma unroll
            for (int l = 0; l < NT; ++l)
                pw[l] = *reinterpret_cast<const float4*>(
                    &W[(long long)(m0 + r + l * 32) * K + kn + kk]);
        }
#pragma unroll
        for (int ks = 0; ks < 4; ++ks) {
            const int kb = ks * 8 + (lane & 3);
            unsigned a[4][4];
#pragma unroll
            for (int mt = 0; mt < 4; ++mt) {
                const int rowb = wn + mt * 16 + (lane >> 2);
                a[mt][0] = __float_as_uint(As[rowb * SSTR_ + kb]);
                a[mt][1] = __float_as_uint(As[(rowb + 8) * SSTR_ + kb]);
                a[mt][2] = __float_as_uint(As[rowb * SSTR_ + kb + 4]);
                a[mt][3] = __float_as_uint(As[(rowb + 8) * SSTR_ + kb + 4]);
            }
#pragma unroll
            for (int nt = 0; nt < NT; ++nt) {
                const int colb = wm + nt * 8 + (lane >> 2);
                unsigned b0 = __float_as_uint(Bs[colb * SSTR_ + kb]);
                unsigned b1 = __float_as_uint(Bs[colb * SSTR_ + kb + 4]);
#pragma unroll
                for (int mt = 0; mt < 4; ++mt) {
                    asm volatile(
                        "mma.sync.aligned.m16n8k8.row.col.f32.tf32.tf32.f32 "
                        "{%0,%1,%2,%3}, {%4,%5,%6,%7}, {%8,%9}, {%0,%1,%2,%3};"
                        : "+f"(acc[mt][nt][0]), "+f"(acc[mt][nt][1]),
                          "+f"(acc[mt][nt][2]), "+f"(acc[mt][nt][3])
                        : "r"(a[mt][0]), "r"(a[mt][1]), "r"(a[mt][2]), "r"(a[mt][3]),
                          "r"(b0), "r"(b1));
                }
            }
        }
        __syncthreads();
    }

    // ---- epilogue: bias + store + per-channel BN partials -------------------
    float sS[NT][2], sQ[NT][2];
#pragma unroll
    for (int nt = 0; nt < NT; ++nt)
        sS[nt][0] = sS[nt][1] = sQ[nt][0] = sQ[nt][1] = 0.f;

#pragma unroll
    for (int mt = 0; mt < 4; ++mt) {
        const int row = n0 + wn + mt * 16 + (lane >> 2);
#pragma unroll
        for (int nt = 0; nt < NT; ++nt) {
            const int col = m0 + wm + nt * 8 + 2 * (lane & 3);
            const float bv0 = bias[col], bv1 = bias[col + 1];
            const float v00 = acc[mt][nt][0] + bv0, v01 = acc[mt][nt][1] + bv1;
            const float v10 = acc[mt][nt][2] + bv0, v11 = acc[mt][nt][3] + bv1;
            *reinterpret_cast<float2*>(&C[(long long)row * M + col])       = make_float2(v00, v01);
            *reinterpret_cast<float2*>(&C[(long long)(row + 8) * M + col]) = make_float2(v10, v11);
            sS[nt][0] += v00 + v10;
            sS[nt][1] += v01 + v11;
            sQ[nt][0] += v00 * v00 + v10 * v10;
            sQ[nt][1] += v01 * v01 + v11 * v11;
        }
    }
    // butterfly over lanes sharing the same (lane&3): sums this warp's 64 points
#pragma unroll
    for (int nt = 0; nt < NT; ++nt)
#pragma unroll
        for (int e = 0; e < 2; ++e) {
#pragma unroll
            for (int o = 4; o < 32; o <<= 1) {
                sS[nt][e] += __shfl_xor_sync(0xFFFFFFFFu, sS[nt][e], o);
                sQ[nt][e] += __shfl_xor_sync(0xFFFFFFFFu, sQ[nt][e], o);
            }
        }
    if (lane < 4) {
#pragma unroll
        for (int nt = 0; nt < NT; ++nt) {
            const int ch = wm + nt * 8 + 2 * lane;
            red[pg * BN + ch]           = sS[nt][0];
            red[pg * BN + ch + 1]       = sS[nt][1];
            red[2 * BN + pg * BN + ch]     = sQ[nt][0];
            red[2 * BN + pg * BN + ch + 1] = sQ[nt][1];
        }
    }
    __syncthreads();
    if (tid < BN) {
        psum[(long long)blockIdx.x * M + m0 + tid] = red[tid] + red[BN + tid];
        psq [(long long)blockIdx.x * M + m0 + tid] = red[2 * BN + tid] + red[3 * BN + tid];
    }
}

// ----------------------------- BN finalize -----------------------------------
// warp-per-channel fold of 512 chunks (deterministic shfl tree).
__global__ void bn_finalize_kernel(const float* __restrict__ psum,
                                   const float* __restrict__ psq,
                                   const float* __restrict__ g,
                                   const float* __restrict__ be,
                                   int C,
                                   float* __restrict__ a,
                                   float* __restrict__ sh) {
    const int c    = blockIdx.x * 8 + (threadIdx.x >> 5);
    const int lane = threadIdx.x & 31;
    float s = 0.f, s2 = 0.f;
    for (int i = lane; i < NCHUNK_; i += 32) { s += psum[i * C + c]; s2 += psq[i * C + c]; }
#pragma unroll
    for (int o = 16; o; o >>= 1) {
        s  += __shfl_xor_sync(0xFFFFFFFFu, s,  o);
        s2 += __shfl_xor_sync(0xFFFFFFFFu, s2, o);
    }
    if (lane == 0) {
        const float inv = 1.f / (float)NP_;
        const float mu  = s * inv;
        const float var = s2 * inv - mu * mu;
        const float r   = rsqrtf(var + 1e-5f);
        const float aa  = g[c] * r;
        a[c]  = aa;
        sh[c] = be[c] - mu * aa;
    }
}

// Final layer: normalize + relu + transpose [NP][128] -> out [B][128][NY].
__global__ void bn_final_out_kernel(const float* __restrict__ H,
                                    const float* __restrict__ a,
                                    const float* __restrict__ sh,
                                    float* __restrict__ out) {
    __shared__ float t[C3_][33];
    const int tid = threadIdx.x;
    const int p0  = blockIdx.x * 32;
    for (int idx = tid; idx < 32 * C3_; idx += 256) {
        const int pl = idx >> 7;        // point within tile
        const int c  = idx & 127;       // channel
        t[c][pl] = H[(long long)(p0 + pl) * C3_ + c];
    }
    __syncthreads();
    for (int idx = tid; idx < C3_ * 32; idx += 256) {
        const int c  = idx >> 5;
        const int pl = idx & 31;
        const float v = fmaxf(0.f, fmaf(t[c][pl], a[c], sh[c]));
        const int p = p0 + pl;
        const int b = p >> 14;          // p / NY_
        const int n = p & (NY_ - 1);
        out[((long long)b * C3_ + c) * NY_ + n] = v;
    }
}

// ----------------------------- launch ---------------------------------------
extern "C" void kernel_launch(void* const* d_in, const int* in_sizes, int n_in,
                              void* d_out, int out_size) {
    (void)in_sizes; (void)n_in; (void)out_size;
    const float* yp  = (const float*)d_in[0];
    const float* yf  = (const float*)d_in[1];
    const float* xp  = (const float*)d_in[2];
    const float* xf  = (const float*)d_in[3];
    const float* W1  = (const float*)d_in[4];
    const float* b1  = (const float*)d_in[5];
    const float* g1  = (const float*)d_in[6];
    const float* be1 = (const float*)d_in[7];
    const float* W2  = (const float*)d_in[8];
    const float* b2  = (const float*)d_in[9];
    const float* g2  = (const float*)d_in[10];
    const float* be2 = (const float*)d_in[11];
    const float* W3  = (const float*)d_in[12];
    const float* b3  = (const float*)d_in[13];
    const float* g3  = (const float*)d_in[14];
    const float* be3 = (const float*)d_in[15];
    float* out = (float*)d_out;

    float *X0, *H1, *H2, *H3, *psum, *psq, *a, *sh;
    cudaGetSymbolAddress((void**)&X0,   g_X0);
    cudaGetSymbolAddress((void**)&H1,   g_H1);
    cudaGetSymbolAddress((void**)&H2,   g_H2);
    cudaGetSymbolAddress((void**)&H3,   g_H3);
    cudaGetSymbolAddress((void**)&psum, g_psum);
    cudaGetSymbolAddress((void**)&psq,  g_psq);
    cudaGetSymbolAddress((void**)&a,    g_a);
    cudaGetSymbolAddress((void**)&sh,   g_sh);

    static int attr_set = 0;
    if (!attr_set) {
        cudaFuncSetAttribute(knn_interp_kernel,
                             cudaFuncAttributeMaxDynamicSharedMemorySize,
                             NX_ * (int)sizeof(float4));
        cudaFuncSetAttribute(gemm_mma_kernel<256, false>,
                             cudaFuncAttributeMaxDynamicSharedMemorySize,
                             gemm_smem_bytes(256));
        cudaFuncSetAttribute(gemm_mma_kernel<256, true>,
                             cudaFuncAttributeMaxDynamicSharedMemorySize,
                             gemm_smem_bytes(256));
        cudaFuncSetAttribute(gemm_mma_kernel<128, true>,
                             cudaFuncAttributeMaxDynamicSharedMemorySize,
                             gemm_smem_bytes(128));
        attr_set = 1;
    }

    // 1) KNN + interpolation -> X0 [NP][384]
    knn_interp_kernel<<<dim3(NY_ / 256, B_), 256, NX_ * sizeof(float4)>>>(yp, yf, xp, xf);

    // 2) Layer 1: 384 -> 512 (BN stats fused in epilogue)
    gemm_mma_kernel<256, false><<<dim3(NP_ / 128, C1_ / 256), 256, gemm_smem_bytes(256)>>>(
        W1, X0, b1, nullptr, nullptr, H1, psum, psq, C1_, DIM_);
    bn_finalize_kernel<<<C1_ / 8, 256>>>(psum, psq, g1, be1, C1_, a, sh);

    // 3) Layer 2: 512 -> 256 (BN1+relu fused into A staging)
    gemm_mma_kernel<256, true><<<dim3(NP_ / 128, C2_ / 256), 256, gemm_smem_bytes(256)>>>(
        W2, H1, b2, a, sh, H2, psum, psq, C2_, C1_);
    bn_finalize_kernel<<<C2_ / 8, 256>>>(psum, psq, g2, be2, C2_, a, sh);

    // 4) Layer 3: 256 -> 128 (BN2+relu fused into A staging)
    gemm_mma_kernel<128, true><<<dim3(NP_ / 128, C3_ / 128), 256, gemm_smem_bytes(128)>>>(
        W3, H2, b3, a, sh, H3, psum, psq, C3_, C2_);
    bn_finalize_kernel<<<C3_ / 8, 256>>>(psum, psq, g3, be3, C3_, a, sh);

    // 5) final normalize + relu + transpose -> out [B,128,NY]
    bn_final_out_kernel<<<NP_ / 32, 256>>>(H3, a, sh, out);
}